// round 1
// baseline (speedup 1.0000x reference)
#include <cuda_runtime.h>

// WeightedDiceLoss fused kernel for GB300 (sm_103a)
// weight = 1 + 5*|boxavg31(target) - target| (zero pad, /961 always)
// out = 1 - (2*sum(in*t*w) + 1) / (sum(in*w) + sum(t*w) + 1)

#define Wd   512
#define Hd   512
#define Rr   64                 // output rows per CTA slab
#define HALO 15
#define SLAB (Rr + 2*HALO)      // 94 rows resident
#define INV_KK2 (1.0f/961.0f)

__device__ float g_part[3 * 4096];   // per-block partial sums (I, A, B)

__global__ __launch_bounds__(512, 1)
void wdice_main(const float* __restrict__ input,
                const float* __restrict__ target,
                int slabsPerImg)
{
    extern __shared__ float P[];               // [SLAB][512] row-prefix sums of target
    const int tid  = threadIdx.x;
    const int wid  = tid >> 5;
    const int lane = tid & 31;
    const int img  = blockIdx.x / slabsPerImg;
    const int slab = blockIdx.x % slabsPerImg;
    const int r0   = slab * Rr;
    const size_t imgOff = (size_t)img * (size_t)(Hd * Wd);

    // ---- Phase 1: load target slab rows; store per-row INCLUSIVE prefix sums.
    // Each warp owns rows j = wid, wid+16, ... ; each lane owns 16 contiguous cols.
    for (int j = wid; j < SLAB; j += 16) {
        const int gr = r0 - HALO + j;
        float v[16];
        if (gr >= 0 && gr < Hd) {
            const float4* row = (const float4*)(target + imgOff + (size_t)gr * Wd);
            #pragma unroll
            for (int q = 0; q < 4; q++) {
                float4 f = row[lane * 4 + q];
                v[4*q+0] = f.x; v[4*q+1] = f.y; v[4*q+2] = f.z; v[4*q+3] = f.w;
            }
            #pragma unroll
            for (int i = 1; i < 16; i++) v[i] += v[i-1];
        } else {
            #pragma unroll
            for (int i = 0; i < 16; i++) v[i] = 0.f;
        }
        // exclusive warp scan of per-lane totals
        float tot = v[15];
        float s = tot;
        #pragma unroll
        for (int o = 1; o < 32; o <<= 1) {
            float n = __shfl_up_sync(0xffffffffu, s, o);
            if (lane >= o) s += n;
        }
        const float ex = s - tot;
        #pragma unroll
        for (int i = 0; i < 16; i++) v[i] += ex;

        float4* dst = (float4*)(P + j * Wd + lane * 16);
        #pragma unroll
        for (int q = 0; q < 4; q++)
            dst[q] = make_float4(v[4*q], v[4*q+1], v[4*q+2], v[4*q+3]);
    }
    __syncthreads();

    // ---- Phase 2: vertical sliding window; thread = column c.
    const int c  = tid;
    const int hi = (c + HALO < Wd - 1) ? (c + HALO) : (Wd - 1);
    const int lo = c - (HALO + 1);                 // valid iff >= 0

    // init vsum over slab rows [0, 30) == global rows [r0-15, r0+15)
    float vsum = 0.f;
    #pragma unroll 6
    for (int j = 0; j < 2 * HALO; j++) {
        float h = P[j * Wd + hi];
        if (lo >= 0) h -= P[j * Wd + lo];
        vsum += h;
    }

    float aI = 0.f, aA = 0.f, aB = 0.f;
    const float* inp = input + imgOff + (size_t)r0 * Wd + c;

    #pragma unroll 4
    for (int k = 0; k < Rr; k++) {
        // add entering row (slab idx k+30): window now covers rows k..k+30
        float hadd = P[(k + 2 * HALO) * Wd + hi];
        if (lo >= 0) hadd -= P[(k + 2 * HALO) * Wd + lo];
        vsum += hadd;

        // recover raw target at slab row k+15 from the prefix
        float t = P[(k + HALO) * Wd + c];
        if (c >= 1) t -= P[(k + HALO) * Wd + c - 1];

        const float in = inp[k * Wd];
        const float w  = fmaf(5.f, fabsf(fmaf(vsum, INV_KK2, -t)), 1.f);
        const float tw = t * w;
        aI = fmaf(in, tw, aI);
        aA = fmaf(in, w,  aA);
        aB += tw;

        // drop leaving row (slab idx k)
        float hsub = P[k * Wd + hi];
        if (lo >= 0) hsub -= P[k * Wd + lo];
        vsum -= hsub;
    }

    // ---- Block reduction (fixed order -> deterministic)
    #pragma unroll
    for (int o = 16; o > 0; o >>= 1) {
        aI += __shfl_down_sync(0xffffffffu, aI, o);
        aA += __shfl_down_sync(0xffffffffu, aA, o);
        aB += __shfl_down_sync(0xffffffffu, aB, o);
    }
    __syncthreads();                 // done reading P; safe to reuse
    if (lane == 0) { P[wid] = aI; P[16 + wid] = aA; P[32 + wid] = aB; }
    __syncthreads();
    if (tid == 0) {
        float I = 0.f, A = 0.f, B = 0.f;
        #pragma unroll
        for (int i = 0; i < 16; i++) { I += P[i]; A += P[16 + i]; B += P[32 + i]; }
        g_part[blockIdx.x * 3 + 0] = I;
        g_part[blockIdx.x * 3 + 1] = A;
        g_part[blockIdx.x * 3 + 2] = B;
    }
}

__global__ void wdice_finalize(int nb, float* __restrict__ out)
{
    __shared__ float sI[256], sA[256], sB[256];
    const int t = threadIdx.x;
    float i = 0.f, a = 0.f, b = 0.f;
    for (int j = t; j < nb; j += 256) {
        i += g_part[3 * j + 0];
        a += g_part[3 * j + 1];
        b += g_part[3 * j + 2];
    }
    sI[t] = i; sA[t] = a; sB[t] = b;
    __syncthreads();
    #pragma unroll
    for (int o = 128; o > 0; o >>= 1) {
        if (t < o) { sI[t] += sI[t + o]; sA[t] += sA[t + o]; sB[t] += sB[t + o]; }
        __syncthreads();
    }
    if (t == 0)
        out[0] = 1.f - (2.f * sI[0] + 1.f) / (sA[0] + sB[0] + 1.f);
}

extern "C" void kernel_launch(void* const* d_in, const int* in_sizes, int n_in,
                              void* d_out, int out_size)
{
    const float* input  = (const float*)d_in[0];
    const float* target = (const float*)d_in[1];
    const int nImg = in_sizes[0] / (Hd * Wd);
    const int slabsPerImg = Hd / Rr;            // 8
    const int grid = nImg * slabsPerImg;        // 512 for B=64
    const size_t smem = (size_t)SLAB * Wd * sizeof(float);   // 192512 B

    cudaFuncSetAttribute(wdice_main,
                         cudaFuncAttributeMaxDynamicSharedMemorySize, (int)smem);
    wdice_main<<<grid, 512, smem>>>(input, target, slabsPerImg);
    wdice_finalize<<<1, 256>>>(grid, (float*)d_out);
}

// round 2
// speedup vs baseline: 1.2883x; 1.2883x over previous
#include <cuda_runtime.h>

// WeightedDiceLoss fused kernel for GB300 (sm_103a) — streaming ring version
// weight = 1 + 5*|boxavg31(target) - target| (zero pad, /961)
// out = 1 - (2*sum(in*t*w) + 1) / (sum(in*w) + sum(t*w) + 1)

#define Wd    512
#define Hd    512
#define Rr    128                  // output rows per CTA slab
#define HALO  15
#define SLABR (Rr + 2*HALO)        // 158 rows streamed per CTA
#define RING  48                   // ring rows resident (>= 31 + 16 + margin)
#define INV_KK2 (1.0f/961.0f)

__device__ float g_part[3 * 1024];     // per-block partials (I, A, B)
__device__ unsigned int g_count = 0;   // completion counter (reset by last block)

__global__ __launch_bounds__(512, 2)
void wdice_main(const float* __restrict__ input,
                const float* __restrict__ target,
                int slabsPerImg,
                float* __restrict__ out)
{
    extern __shared__ float P[];            // [RING][512] row prefix sums
    const int tid  = threadIdx.x;
    const int wid  = tid >> 5;
    const int lane = tid & 31;
    const int img  = blockIdx.x / slabsPerImg;
    const int slab = blockIdx.x % slabsPerImg;
    const int r0   = slab * Rr;
    const size_t imgOff = (size_t)img * (size_t)(Hd * Wd);

    // ---- Producer: warp `wid` builds prefix-sum of target row (r0-15+j) into ring slot j%RING.
    auto produce = [&](int pr) {
        const int j = pr + wid;                 // one row per warp, 16 rows per call
        if (j >= SLABR) return;
        const int gr = r0 - HALO + j;
        float v[16];
        if (gr >= 0 && gr < Hd) {
            const float4* row = (const float4*)(target + imgOff + (size_t)gr * Wd);
            #pragma unroll
            for (int q = 0; q < 4; q++) {
                float4 f = row[lane * 4 + q];
                v[4*q+0] = f.x; v[4*q+1] = f.y; v[4*q+2] = f.z; v[4*q+3] = f.w;
            }
            #pragma unroll
            for (int i = 1; i < 16; i++) v[i] += v[i-1];
            float tot = v[15];
            float s = tot;
            #pragma unroll
            for (int o = 1; o < 32; o <<= 1) {
                float n = __shfl_up_sync(0xffffffffu, s, o);
                if (lane >= o) s += n;
            }
            const float ex = s - tot;
            #pragma unroll
            for (int i = 0; i < 16; i++) v[i] += ex;
        } else {
            #pragma unroll
            for (int i = 0; i < 16; i++) v[i] = 0.f;
        }
        float4* dst = (float4*)(P + (j % RING) * Wd + lane * 16);
        #pragma unroll
        for (int q = 0; q < 4; q++)
            dst[q] = make_float4(v[4*q], v[4*q+1], v[4*q+2], v[4*q+3]);
    };

    // Prime ring with slab rows 0..47
    produce(0); produce(16); produce(32);
    __syncthreads();

    // ---- Consumer: thread = column c, vertical sliding window over hsum rows.
    const int c  = tid;
    const int hi = (c + HALO < Wd - 1) ? (c + HALO) : (Wd - 1);
    const int lo = c - (HALO + 1);                 // valid iff >= 0

    float vsum = 0.f;
    #pragma unroll 6
    for (int j = 0; j < 2 * HALO; j++) {           // slab rows 0..29
        float h = P[j * Wd + hi];
        if (lo >= 0) h -= P[j * Wd + lo];
        vsum += h;
    }

    float aI = 0.f, aA = 0.f, aB = 0.f;
    const float* inp = input + imgOff + (size_t)r0 * Wd + c;

    // rolling ring pointers (rows: add = k+30, t = k+15, sub = k)
    const float* rAdd = P + 30 * Wd;
    const float* rT   = P + 15 * Wd;
    const float* rSub = P;
    const float* Pend = P + RING * Wd;

    for (int ch = 0; ch < Rr / 16; ch++) {
        #pragma unroll 4
        for (int kk = 0; kk < 16; kk++) {
            const int k = ch * 16 + kk;
            float hadd = rAdd[hi];
            if (lo >= 0) hadd -= rAdd[lo];
            vsum += hadd;

            float t = rT[c];
            if (c >= 1) t -= rT[c - 1];

            const float in = inp[k * Wd];
            const float w  = fmaf(5.f, fabsf(fmaf(vsum, INV_KK2, -t)), 1.f);
            const float tw = t * w;
            aI = fmaf(in, tw, aI);
            aA = fmaf(in, w,  aA);
            aB += tw;

            float hsub = rSub[hi];
            if (lo >= 0) hsub -= rSub[lo];
            vsum -= hsub;

            rAdd += Wd; if (rAdd == Pend) rAdd = P;
            rT   += Wd; if (rT   == Pend) rT   = P;
            rSub += Wd; if (rSub == Pend) rSub = P;
        }
        __syncthreads();                    // done reading rows ch*16..ch*16+15
        if (ch < Rr / 16 - 1) {
            produce(48 + ch * 16);          // overwrite slots of rows ch*16..ch*16+15
            __syncthreads();
        }
    }

    // ---- Block reduction (fixed order -> deterministic)
    #pragma unroll
    for (int o = 16; o > 0; o >>= 1) {
        aI += __shfl_down_sync(0xffffffffu, aI, o);
        aA += __shfl_down_sync(0xffffffffu, aA, o);
        aB += __shfl_down_sync(0xffffffffu, aB, o);
    }
    if (lane == 0) { P[wid] = aI; P[16 + wid] = aA; P[32 + wid] = aB; }
    __syncthreads();
    __shared__ unsigned int sIsLast;
    if (tid == 0) {
        float I = 0.f, A = 0.f, B = 0.f;
        #pragma unroll
        for (int i = 0; i < 16; i++) { I += P[i]; A += P[16 + i]; B += P[32 + i]; }
        g_part[blockIdx.x * 3 + 0] = I;
        g_part[blockIdx.x * 3 + 1] = A;
        g_part[blockIdx.x * 3 + 2] = B;
        __threadfence();
        sIsLast = (atomicAdd(&g_count, 1u) == gridDim.x - 1u);
    }
    __syncthreads();

    // ---- Last block finalizes (fixed-order reduction -> deterministic)
    if (sIsLast) {
        const int nb = gridDim.x;
        float i = 0.f, a = 0.f, b = 0.f;
        for (int j = tid; j < nb; j += 512) {
            i += g_part[3 * j + 0];
            a += g_part[3 * j + 1];
            b += g_part[3 * j + 2];
        }
        #pragma unroll
        for (int o = 16; o > 0; o >>= 1) {
            i += __shfl_down_sync(0xffffffffu, i, o);
            a += __shfl_down_sync(0xffffffffu, a, o);
            b += __shfl_down_sync(0xffffffffu, b, o);
        }
        __syncthreads();
        if (lane == 0) { P[wid] = i; P[16 + wid] = a; P[32 + wid] = b; }
        __syncthreads();
        if (tid == 0) {
            float I = 0.f, A = 0.f, B = 0.f;
            #pragma unroll
            for (int q = 0; q < 16; q++) { I += P[q]; A += P[16 + q]; B += P[32 + q]; }
            out[0] = 1.f - (2.f * I + 1.f) / (A + B + 1.f);
            g_count = 0;                     // reset for next graph replay
        }
    }
}

extern "C" void kernel_launch(void* const* d_in, const int* in_sizes, int n_in,
                              void* d_out, int out_size)
{
    const float* input  = (const float*)d_in[0];
    const float* target = (const float*)d_in[1];
    const int nImg = in_sizes[0] / (Hd * Wd);
    const int slabsPerImg = Hd / Rr;               // 4
    const int grid = nImg * slabsPerImg;           // 256 for B=64
    const size_t smem = (size_t)RING * Wd * sizeof(float);   // 98304 B

    cudaFuncSetAttribute(wdice_main,
                         cudaFuncAttributeMaxDynamicSharedMemorySize, (int)smem);
    wdice_main<<<grid, 512, smem>>>(input, target, slabsPerImg, (float*)d_out);
}

// round 3
// speedup vs baseline: 1.5536x; 1.2059x over previous
#include <cuda_runtime.h>

// WeightedDiceLoss fused kernel (sm_103a) — producer computes hsum rows,
// consumer does 2 LDS/row + coalesced LDG for t and input.
// weight = 1 + 5*|boxavg31(target) - target|, zero pad, /961
// out = 1 - (2*sum(in*t*w) + 1) / (sum(in*w) + sum(t*w) + 1)

#define Wd    512
#define Hd    512
#define Rr    128                  // output rows per CTA slab
#define HALO  15
#define SLABR (Rr + 2*HALO)        // 158 rows streamed per CTA
#define RING  48                   // hsum ring rows (31 window + 16 chunk + 1)
#define NCHUNK (Rr / 16)           // 8
#define INV_KK2 (1.0f/961.0f)

__device__ float g_part[3 * 1024];
__device__ unsigned int g_count = 0;

__global__ __launch_bounds__(512, 2)
void wdice_main(const float* __restrict__ input,
                const float* __restrict__ target,
                int slabsPerImg,
                float* __restrict__ out)
{
    extern __shared__ float HS[];           // [RING][512] horizontal box sums
    const int tid  = threadIdx.x;
    const int wid  = tid >> 5;
    const int lane = tid & 31;
    const int img  = blockIdx.x / slabsPerImg;
    const int slab = blockIdx.x % slabsPerImg;
    const int r0   = slab * Rr;
    const size_t imgOff = (size_t)img * (size_t)(Hd * Wd);

    // ---- Producer: warp `wid` computes hsum of target row (r0-15+j),
    // hsum[c] = Pfull[min(c+15,511)] - (c>=16 ? Pfull[c-16] : 0), stores to ring slot j%RING.
    auto produce = [&](int pr) {
        const int j = pr + wid;                 // one row per warp (16 rows/call)
        if (j >= SLABR) return;
        const int gr = r0 - HALO + j;
        float4* dst = (float4*)(HS + (j % RING) * Wd + lane * 16);
        if (gr < 0 || gr >= Hd) {
            const float4 z = make_float4(0.f, 0.f, 0.f, 0.f);
            #pragma unroll
            for (int q = 0; q < 4; q++) dst[q] = z;
            return;
        }
        float v[16];
        const float4* row = (const float4*)(target + imgOff + (size_t)gr * Wd);
        #pragma unroll
        for (int q = 0; q < 4; q++) {
            float4 f = row[lane * 4 + q];
            v[4*q+0] = f.x; v[4*q+1] = f.y; v[4*q+2] = f.z; v[4*q+3] = f.w;
        }
        #pragma unroll
        for (int i = 1; i < 16; i++) v[i] += v[i-1];
        // exclusive warp scan of lane totals -> v[] becomes full-row prefix
        float tot = v[15];
        float s = tot;
        #pragma unroll
        for (int o = 1; o < 32; o <<= 1) {
            float n = __shfl_up_sync(0xffffffffu, s, o);
            if (lane >= o) s += n;
        }
        const float ex = s - tot;
        #pragma unroll
        for (int i = 0; i < 16; i++) v[i] += ex;
        const float vtop = v[15];               // full prefix at lane's col 16L+15

        // hsum[i] = P[c+15] - P[c-16]; neighbors via single-step shuffles
        float h[16];
        #pragma unroll
        for (int i = 0; i < 16; i++) {
            float prv = __shfl_up_sync(0xffffffffu, v[i], 1);    // P[16(L-1)+i]
            if (lane == 0) prv = 0.f;
            float hiP;
            if (i == 0) {
                hiP = vtop;                                       // P[16L+15]
            } else {
                float nxt = __shfl_down_sync(0xffffffffu, v[i-1], 1); // P[16(L+1)+i-1]
                hiP = (lane == 31) ? vtop : nxt;                  // clamp to row total
            }
            h[i] = hiP - prv;
        }
        #pragma unroll
        for (int q = 0; q < 4; q++)
            dst[q] = make_float4(h[4*q], h[4*q+1], h[4*q+2], h[4*q+3]);
    };

    // Prime ring with slab rows 0..47
    produce(0); produce(16); produce(32);
    __syncthreads();

    // ---- Consumer: thread = column c.
    const int c = tid;
    float vsum = 0.f;
    #pragma unroll
    for (int j = 0; j <= 2 * HALO; j++)          // rows 0..30 (window for k=0)
        vsum += HS[j * Wd + c];

    float aI = 0.f, aA = 0.f, aB = 0.f;
    const float* inp = input  + imgOff + (size_t)r0 * Wd + c;
    const float* tgt = target + imgOff + (size_t)r0 * Wd + c;

    #pragma unroll
    for (int ch = 0; ch < NCHUNK; ch++) {
        #pragma unroll
        for (int kk = 0; kk < 16; kk++) {
            const int k = ch * 16 + kk;
            // compile-time ring offsets
            const int jAdd = ((k + 31) % RING) * Wd;   // row entering next window
            const int jSub = (k % RING) * Wd;          // row leaving

            const float t  = tgt[k * Wd];
            const float in = inp[k * Wd];
            const float w  = fmaf(5.f, fabsf(fmaf(vsum, INV_KK2, -t)), 1.f);
            const float tw = t * w;
            aI = fmaf(in, tw, aI);
            aA = fmaf(in, w,  aA);
            aB += tw;

            if (k < Rr - 1)
                vsum += (HS[jAdd + c] - HS[jSub + c]);
        }
        __syncthreads();                    // rows ch*16..+15 dead
        if (ch < NCHUNK - 1) {
            produce(48 + ch * 16);          // refill their ring slots
            __syncthreads();
        }
    }

    // ---- Block reduction (fixed order -> deterministic)
    #pragma unroll
    for (int o = 16; o > 0; o >>= 1) {
        aI += __shfl_down_sync(0xffffffffu, aI, o);
        aA += __shfl_down_sync(0xffffffffu, aA, o);
        aB += __shfl_down_sync(0xffffffffu, aB, o);
    }
    if (lane == 0) { HS[wid] = aI; HS[16 + wid] = aA; HS[32 + wid] = aB; }
    __syncthreads();
    __shared__ unsigned int sIsLast;
    if (tid == 0) {
        float I = 0.f, A = 0.f, B = 0.f;
        #pragma unroll
        for (int i = 0; i < 16; i++) { I += HS[i]; A += HS[16 + i]; B += HS[32 + i]; }
        g_part[blockIdx.x * 3 + 0] = I;
        g_part[blockIdx.x * 3 + 1] = A;
        g_part[blockIdx.x * 3 + 2] = B;
        __threadfence();
        sIsLast = (atomicAdd(&g_count, 1u) == gridDim.x - 1u);
    }
    __syncthreads();

    if (sIsLast) {
        const int nb = gridDim.x;
        float i = 0.f, a = 0.f, b = 0.f;
        for (int j = tid; j < nb; j += 512) {
            i += g_part[3 * j + 0];
            a += g_part[3 * j + 1];
            b += g_part[3 * j + 2];
        }
        #pragma unroll
        for (int o = 16; o > 0; o >>= 1) {
            i += __shfl_down_sync(0xffffffffu, i, o);
            a += __shfl_down_sync(0xffffffffu, a, o);
            b += __shfl_down_sync(0xffffffffu, b, o);
        }
        __syncthreads();
        if (lane == 0) { HS[wid] = i; HS[16 + wid] = a; HS[32 + wid] = b; }
        __syncthreads();
        if (tid == 0) {
            float I = 0.f, A = 0.f, B = 0.f;
            #pragma unroll
            for (int q = 0; q < 16; q++) { I += HS[q]; A += HS[16 + q]; B += HS[32 + q]; }
            out[0] = 1.f - (2.f * I + 1.f) / (A + B + 1.f);
            g_count = 0;
        }
    }
}

extern "C" void kernel_launch(void* const* d_in, const int* in_sizes, int n_in,
                              void* d_out, int out_size)
{
    const float* input  = (const float*)d_in[0];
    const float* target = (const float*)d_in[1];
    const int nImg = in_sizes[0] / (Hd * Wd);
    const int slabsPerImg = Hd / Rr;               // 4
    const int grid = nImg * slabsPerImg;           // 256 for B=64
    const size_t smem = (size_t)RING * Wd * sizeof(float);   // 98304 B

    cudaFuncSetAttribute(wdice_main,
                         cudaFuncAttributeMaxDynamicSharedMemorySize, (int)smem);
    wdice_main<<<grid, 512, smem>>>(input, target, slabsPerImg, (float*)d_out);
}

// round 4
// speedup vs baseline: 1.5616x; 1.0052x over previous
#include <cuda_runtime.h>

// WeightedDiceLoss fused kernel (sm_103a) — pipelined producer version.
// Producer split: prefetch (LDG->regs, issued a full chunk ahead) + scanStore.
// weight = 1 + 5*|boxavg31(target) - target|, zero pad, /961
// out = 1 - (2*sum(in*t*w) + 1) / (sum(in*w) + sum(t*w) + 1)

#define Wd    512
#define Hd    512
#define Rr    128
#define HALO  15
#define SLABR (Rr + 2*HALO)        // 158
#define RING  48
#define NCHUNK (Rr / 16)           // 8
#define INV_KK2 (1.0f/961.0f)

__device__ float g_part[3 * 1024];
__device__ unsigned int g_count = 0;

__global__ __launch_bounds__(512, 2)
void wdice_main(const float* __restrict__ input,
                const float* __restrict__ target,
                int slabsPerImg,
                float* __restrict__ out)
{
    extern __shared__ float HS[];           // [RING][512] horizontal box sums
    const int tid  = threadIdx.x;
    const int wid  = tid >> 5;
    const int lane = tid & 31;
    const int img  = blockIdx.x / slabsPerImg;
    const int slab = blockIdx.x % slabsPerImg;
    const int r0   = slab * Rr;
    const size_t imgOff = (size_t)img * (size_t)(Hd * Wd);

    // LDG of target row (r0-15+pr+wid) into regs; zeros if out of range.
    auto prefetch = [&](int pr, float v[16]) {
        const int j  = pr + wid;
        const int gr = r0 - HALO + j;
        if (j < SLABR && gr >= 0 && gr < Hd) {
            const float4* row = (const float4*)(target + imgOff + (size_t)gr * Wd);
            #pragma unroll
            for (int q = 0; q < 4; q++) {
                float4 f = row[lane * 4 + q];
                v[4*q+0] = f.x; v[4*q+1] = f.y; v[4*q+2] = f.z; v[4*q+3] = f.w;
            }
        } else {
            #pragma unroll
            for (int i = 0; i < 16; i++) v[i] = 0.f;
        }
    };

    // Scan regs -> hsum row -> STS into ring slot (pr+wid)%RING.
    auto scanStore = [&](int pr, float v[16]) {
        const int j = pr + wid;
        if (j >= SLABR) return;
        #pragma unroll
        for (int i = 1; i < 16; i++) v[i] += v[i-1];
        float tot = v[15];
        float s = tot;
        #pragma unroll
        for (int o = 1; o < 32; o <<= 1) {
            float n = __shfl_up_sync(0xffffffffu, s, o);
            if (lane >= o) s += n;
        }
        const float ex = s - tot;
        #pragma unroll
        for (int i = 0; i < 16; i++) v[i] += ex;
        const float vtop = v[15];

        float h[16];
        #pragma unroll
        for (int i = 0; i < 16; i++) {
            float prv = __shfl_up_sync(0xffffffffu, v[i], 1);
            if (lane == 0) prv = 0.f;
            float hiP;
            if (i == 0) {
                hiP = vtop;
            } else {
                float nxt = __shfl_down_sync(0xffffffffu, v[i-1], 1);
                hiP = (lane == 31) ? vtop : nxt;
            }
            h[i] = hiP - prv;
        }
        float4* dst = (float4*)(HS + (j % RING) * Wd + lane * 16);
        #pragma unroll
        for (int q = 0; q < 4; q++)
            dst[q] = make_float4(h[4*q], h[4*q+1], h[4*q+2], h[4*q+3]);
    };

    // ---- Priming: overlap LDGs with scans using two buffers.
    float pw[16];
    {
        float pa[16];
        prefetch(0,  pa);
        prefetch(16, pw);
        scanStore(0, pa);
        prefetch(32, pa);
        scanStore(16, pw);
        prefetch(48, pw);            // refill data for after chunk 0
        scanStore(32, pa);
    }
    __syncthreads();

    // ---- Consumer: thread = column c.
    const int c = tid;
    float vsum = 0.f;
    #pragma unroll
    for (int j = 0; j <= 2 * HALO; j++)
        vsum += HS[j * Wd + c];

    float aI = 0.f, aA = 0.f, aB = 0.f;
    const float* inp = input  + imgOff + (size_t)r0 * Wd + c;
    const float* tgt = target + imgOff + (size_t)r0 * Wd + c;

    #pragma unroll
    for (int ch = 0; ch < NCHUNK; ch++) {
        #pragma unroll
        for (int kk = 0; kk < 16; kk++) {
            const int k = ch * 16 + kk;
            const int jAdd = ((k + 31) % RING) * Wd;
            const int jSub = (k % RING) * Wd;

            const float t  = tgt[k * Wd];
            const float in = inp[k * Wd];
            const float w  = fmaf(5.f, fabsf(fmaf(vsum, INV_KK2, -t)), 1.f);
            const float tw = t * w;
            aI = fmaf(in, tw, aI);
            aA = fmaf(in, w,  aA);
            aB += tw;

            if (k < Rr - 1)
                vsum += (HS[jAdd + c] - HS[jSub + c]);
        }
        __syncthreads();                    // rows ch*16..+15 dead
        if (ch < NCHUNK - 1) {
            scanStore(48 + ch * 16, pw);    // uses LDG issued one chunk ago
            if (ch < NCHUNK - 2)
                prefetch(48 + (ch + 1) * 16, pw);  // latency hidden by next consume
            __syncthreads();
        }
    }

    // ---- Block reduction (fixed order -> deterministic)
    #pragma unroll
    for (int o = 16; o > 0; o >>= 1) {
        aI += __shfl_down_sync(0xffffffffu, aI, o);
        aA += __shfl_down_sync(0xffffffffu, aA, o);
        aB += __shfl_down_sync(0xffffffffu, aB, o);
    }
    if (lane == 0) { HS[wid] = aI; HS[16 + wid] = aA; HS[32 + wid] = aB; }
    __syncthreads();
    __shared__ unsigned int sIsLast;
    if (tid == 0) {
        float I = 0.f, A = 0.f, B = 0.f;
        #pragma unroll
        for (int i = 0; i < 16; i++) { I += HS[i]; A += HS[16 + i]; B += HS[32 + i]; }
        g_part[blockIdx.x * 3 + 0] = I;
        g_part[blockIdx.x * 3 + 1] = A;
        g_part[blockIdx.x * 3 + 2] = B;
        __threadfence();
        sIsLast = (atomicAdd(&g_count, 1u) == gridDim.x - 1u);
    }
    __syncthreads();

    if (sIsLast) {
        const int nb = gridDim.x;
        float i = 0.f, a = 0.f, b = 0.f;
        for (int j = tid; j < nb; j += 512) {
            i += g_part[3 * j + 0];
            a += g_part[3 * j + 1];
            b += g_part[3 * j + 2];
        }
        #pragma unroll
        for (int o = 16; o > 0; o >>= 1) {
            i += __shfl_down_sync(0xffffffffu, i, o);
            a += __shfl_down_sync(0xffffffffu, a, o);
            b += __shfl_down_sync(0xffffffffu, b, o);
        }
        __syncthreads();
        if (lane == 0) { HS[wid] = i; HS[16 + wid] = a; HS[32 + wid] = b; }
        __syncthreads();
        if (tid == 0) {
            float I = 0.f, A = 0.f, B = 0.f;
            #pragma unroll
            for (int q = 0; q < 16; q++) { I += HS[q]; A += HS[16 + q]; B += HS[32 + q]; }
            out[0] = 1.f - (2.f * I + 1.f) / (A + B + 1.f);
            g_count = 0;
        }
    }
}

extern "C" void kernel_launch(void* const* d_in, const int* in_sizes, int n_in,
                              void* d_out, int out_size)
{
    const float* input  = (const float*)d_in[0];
    const float* target = (const float*)d_in[1];
    const int nImg = in_sizes[0] / (Hd * Wd);
    const int slabsPerImg = Hd / Rr;               // 4
    const int grid = nImg * slabsPerImg;           // 256
    const size_t smem = (size_t)RING * Wd * sizeof(float);   // 98304 B

    cudaFuncSetAttribute(wdice_main,
                         cudaFuncAttributeMaxDynamicSharedMemorySize, (int)smem);
    wdice_main<<<grid, 512, smem>>>(input, target, slabsPerImg, (float*)d_out);
}

// round 5
// speedup vs baseline: 1.5748x; 1.0085x over previous
#include <cuda_runtime.h>

// WeightedDiceLoss (sm_103a) — warp-specialized producer/consumer with named
// barriers + packed f32x2 consumer math.
// weight = 1 + 5*|boxavg31(target) - target|, zero pad, /961
// out = 1 - (2*sum(in*t*w) + 1) / (sum(in*w) + sum(t*w) + 1)

#define Wd    512
#define Hd    512
#define Rr    128
#define HALO  15
#define SLABR (Rr + 2*HALO)        // 158
#define RING  48
#define NCH   8                    // consumer chunks of 16 rows
#define NPQ   10                   // producer chunks (ceil(158/16))
#define INV_KK2 (1.0f/961.0f)

typedef unsigned long long ull;

#define FMA2(d,a,b,c) asm("fma.rn.f32x2 %0,%1,%2,%3;" : "=l"(d) : "l"(a),"l"(b),"l"(c))
#define MUL2(d,a,b)   asm("mul.rn.f32x2 %0,%1,%2;"    : "=l"(d) : "l"(a),"l"(b))
#define ADD2(d,a,b)   asm("add.rn.f32x2 %0,%1,%2;"    : "=l"(d) : "l"(a),"l"(b))

__device__ __forceinline__ ull pk2(float x, float y) {
    ull r; asm("mov.b64 %0,{%1,%2};" : "=l"(r) : "f"(x), "f"(y)); return r;
}
__device__ __forceinline__ float hsum2(ull v) {
    float a, b; asm("mov.b64 {%0,%1},%2;" : "=f"(a), "=f"(b) : "l"(v)); return a + b;
}
__device__ __forceinline__ void barSyncN(int id) {
    asm volatile("bar.sync %0, 512;" :: "r"(id) : "memory");
}
__device__ __forceinline__ void barArriveN(int id) {
    asm volatile("bar.arrive %0, 512;" :: "r"(id) : "memory");
}
// arrive with a register dependency: forces the vsum chain (and therefore all
// LDS feeding it) to have completed before the arrive issues.
__device__ __forceinline__ void barArriveDep(int id, ull& dep) {
    asm volatile("bar.arrive %1, 512;" : "+l"(dep) : "r"(id) : "memory");
}

__device__ float g_part[3 * 1024];
__device__ unsigned int g_count = 0;

__global__ __launch_bounds__(512, 2)
void wdice_main(const float* __restrict__ input,
                const float* __restrict__ target,
                int slabsPerImg,
                float* __restrict__ out)
{
    extern __shared__ float HS[];           // [RING][512] hsum ring
    const int tid  = threadIdx.x;
    const int wid  = tid >> 5;
    const int lane = tid & 31;
    const int img  = blockIdx.x / slabsPerImg;
    const int slab = blockIdx.x % slabsPerImg;
    const int r0   = slab * Rr;
    const size_t imgOff = (size_t)img * (size_t)(Hd * Wd);

    float aI, aA, aB;

    if (wid < 8) {
        // ======================= PRODUCER (warps 0-7) =======================
        float v0[16], v1[16];

        auto pref = [&](int q, float v[16], int half) {
            const int j  = 16 * q + half * 8 + wid;
            const int gr = r0 - HALO + j;
            if (j < SLABR && gr >= 0 && gr < Hd) {
                const float4* row = (const float4*)(target + imgOff + (size_t)gr * Wd);
                #pragma unroll
                for (int p = 0; p < 4; p++) {
                    float4 f = row[lane * 4 + p];
                    v[4*p+0] = f.x; v[4*p+1] = f.y; v[4*p+2] = f.z; v[4*p+3] = f.w;
                }
            } else {
                #pragma unroll
                for (int i = 0; i < 16; i++) v[i] = 0.f;
            }
        };
        auto scanStore = [&](int q, float v[16], int half) {
            const int j = 16 * q + half * 8 + wid;
            if (j >= SLABR) return;
            #pragma unroll
            for (int i = 1; i < 16; i++) v[i] += v[i-1];
            float tot = v[15], s = tot;
            #pragma unroll
            for (int o = 1; o < 32; o <<= 1) {
                float n = __shfl_up_sync(0xffffffffu, s, o);
                if (lane >= o) s += n;
            }
            const float ex = s - tot;
            #pragma unroll
            for (int i = 0; i < 16; i++) v[i] += ex;
            const float vtop = v[15];
            float h[16];
            #pragma unroll
            for (int i = 0; i < 16; i++) {
                float prv = __shfl_up_sync(0xffffffffu, v[i], 1);
                if (lane == 0) prv = 0.f;
                float hiP;
                if (i == 0) hiP = vtop;
                else {
                    float nxt = __shfl_down_sync(0xffffffffu, v[i-1], 1);
                    hiP = (lane == 31) ? vtop : nxt;
                }
                h[i] = hiP - prv;
            }
            float4* dst = (float4*)(HS + (j % RING) * Wd + lane * 16);
            #pragma unroll
            for (int p = 0; p < 4; p++)
                dst[p] = make_float4(h[4*p], h[4*p+1], h[4*p+2], h[4*p+3]);
        };

        pref(0, v0, 0); pref(0, v1, 1);
        #pragma unroll 1
        for (int q = 0; q < NPQ; q++) {
            if (q >= 3) barSyncN(5 + ((q - 3) & 3));       // wait EMPTY(q-3)
            scanStore(q, v0, 0); scanStore(q, v1, 1);
            __threadfence_block();
            barArriveN(1 + (q & 3));                       // signal FULL(q)
            if (q + 1 < NPQ) { pref(q + 1, v0, 0); pref(q + 1, v1, 1); }
        }
        aI = aA = aB = 0.f;
    } else {
        // ======================= CONSUMER (warps 8-15) ======================
        const int ct = tid - 256;                // column-pair index 0..255
        const ull* HSu = (const ull*)HS;         // row stride 256 pairs
        const ull one2  = pk2(1.f, 1.f);
        const ull neg12 = pk2(-1.f, -1.f);
        const ull five2 = pk2(5.f, 5.f);
        const ull ninv2 = pk2(-INV_KK2, -INV_KK2);
        const ull amask = 0x7FFFFFFF7FFFFFFFull;

        barSyncN(1 + 0);                         // FULL(0)
        barSyncN(1 + 1);                         // FULL(1)

        ull v2 = 0ull;                           // packed (0,0)
        #pragma unroll
        for (int j = 0; j <= 2 * HALO; j++)
            ADD2(v2, v2, HSu[j * 256 + ct]);

        ull aI2 = 0, aA2 = 0, aB2 = 0;
        const ull* tgtU = (const ull*)(target + imgOff + (size_t)r0 * Wd) + ct;
        const ull* inpU = (const ull*)(input  + imgOff + (size_t)r0 * Wd) + ct;

        #pragma unroll 1
        for (int ch = 0; ch < NCH; ch++) {
            barSyncN(1 + ((ch + 2) & 3));        // FULL(ch+2)
            const int base = (16 * ch) % RING;   // 0,16,32,...

            #pragma unroll
            for (int kk = 0; kk < 16; kk++) {
                const ull t2 = tgtU[kk * 256];
                const ull i2 = inpU[kk * 256];
                ull d;  FMA2(d, v2, ninv2, t2);  // t - vsum/961 (packed)
                d &= amask;                      // |.| on both halves
                ull w;  FMA2(w, d, five2, one2);
                ull tw; MUL2(tw, t2, w);
                FMA2(aI2, i2, tw, aI2);
                FMA2(aA2, i2, w,  aA2);
                ADD2(aB2, aB2, tw);

                int ao = base + 31 + kk; if (ao >= RING) ao -= RING;
                const int so = base + kk;        // always < RING
                const ull ar = HSu[ao * 256 + ct];
                const ull sr = HSu[so * 256 + ct];
                ull tmp; ADD2(tmp, v2, ar);
                FMA2(v2, sr, neg12, tmp);        // v += ar - sr
            }
            tgtU += 16 * 256; inpU += 16 * 256;
            if (ch < NCH - 1)
                barArriveDep(5 + (ch & 3), v2);  // signal EMPTY(ch)
        }
        aI = hsum2(aI2); aA = hsum2(aA2); aB = hsum2(aB2);
    }

    // ---- Block reduction (fixed order -> deterministic) ----
    #pragma unroll
    for (int o = 16; o > 0; o >>= 1) {
        aI += __shfl_down_sync(0xffffffffu, aI, o);
        aA += __shfl_down_sync(0xffffffffu, aA, o);
        aB += __shfl_down_sync(0xffffffffu, aB, o);
    }
    __syncthreads();                 // everyone done with HS ring
    if (lane == 0) { HS[wid] = aI; HS[16 + wid] = aA; HS[32 + wid] = aB; }
    __syncthreads();
    __shared__ unsigned int sIsLast;
    if (tid == 0) {
        float I = 0.f, A = 0.f, B = 0.f;
        #pragma unroll
        for (int i = 0; i < 16; i++) { I += HS[i]; A += HS[16 + i]; B += HS[32 + i]; }
        g_part[blockIdx.x * 3 + 0] = I;
        g_part[blockIdx.x * 3 + 1] = A;
        g_part[blockIdx.x * 3 + 2] = B;
        __threadfence();
        sIsLast = (atomicAdd(&g_count, 1u) == gridDim.x - 1u);
    }
    __syncthreads();

    if (sIsLast) {
        const int nb = gridDim.x;
        float i = 0.f, a = 0.f, b = 0.f;
        for (int j = tid; j < nb; j += 512) {
            i += g_part[3 * j + 0];
            a += g_part[3 * j + 1];
            b += g_part[3 * j + 2];
        }
        #pragma unroll
        for (int o = 16; o > 0; o >>= 1) {
            i += __shfl_down_sync(0xffffffffu, i, o);
            a += __shfl_down_sync(0xffffffffu, a, o);
            b += __shfl_down_sync(0xffffffffu, b, o);
        }
        __syncthreads();
        if (lane == 0) { HS[wid] = i; HS[16 + wid] = a; HS[32 + wid] = b; }
        __syncthreads();
        if (tid == 0) {
            float I = 0.f, A = 0.f, B = 0.f;
            #pragma unroll
            for (int q = 0; q < 16; q++) { I += HS[q]; A += HS[16 + q]; B += HS[32 + q]; }
            out[0] = 1.f - (2.f * I + 1.f) / (A + B + 1.f);
            g_count = 0;
        }
    }
}

extern "C" void kernel_launch(void* const* d_in, const int* in_sizes, int n_in,
                              void* d_out, int out_size)
{
    const float* input  = (const float*)d_in[0];
    const float* target = (const float*)d_in[1];
    const int nImg = in_sizes[0] / (Hd * Wd);
    const int slabsPerImg = Hd / Rr;               // 4
    const int grid = nImg * slabsPerImg;           // 256
    const size_t smem = (size_t)RING * Wd * sizeof(float);   // 98304 B

    cudaFuncSetAttribute(wdice_main,
                         cudaFuncAttributeMaxDynamicSharedMemorySize, (int)smem);
    wdice_main<<<grid, 512, smem>>>(input, target, slabsPerImg, (float*)d_out);
}